// round 8
// baseline (speedup 1.0000x reference)
#include <cuda_runtime.h>
#include <cuda_bf16.h>
#include <cstdint>
#include <math.h>

#define BATCH 256
#define SRCLEN 120
#define TGTLEN 24
#define DIN 216
#define HID 1024
#define KPAD 256

#define KC 32                 // K per pipeline chunk
#define NCHUNK_H (HID / KC)   // 32
#define NCHUNK_X (KPAD / KC)  // 8
#define NCHUNK (NCHUNK_H + NCHUNK_X)   // 40 total
#define NCHPG (NCHUNK / 2)             // 20 per warp-group
#define NSTAGE 3                       // stages per group

#define AROW 80               // smem row stride bytes (64B data + 16B pad)
#define OFF_AHI 0
#define OFF_ALO 10240
#define OFF_BHI 20480
#define OFF_BLO 25600
#define STAGE_BYTES 30720
#define GRP_BYTES (NSTAGE * STAGE_BYTES)      // 92160 per group
#define SMEM_TOTAL (2 * GRP_BYTES)            // 184320

// ---------------------------------------------------------------------------
// Static device scratch (no runtime allocation allowed)
// ---------------------------------------------------------------------------
__device__ __nv_bfloat16 g_Whh_hi[4096 * HID];
__device__ __nv_bfloat16 g_Whh_lo[4096 * HID];
__device__ __nv_bfloat16 g_Wih_hi[4096 * KPAD];
__device__ __nv_bfloat16 g_Wih_lo[4096 * KPAD];
__device__ __nv_bfloat16 g_Xsrc_hi[SRCLEN * BATCH * KPAD];
__device__ __nv_bfloat16 g_Xsrc_lo[SRCLEN * BATCH * KPAD];
__device__ __nv_bfloat16 g_xdec_hi[BATCH * KPAD];
__device__ __nv_bfloat16 g_xdec_lo[BATCH * KPAD];
__device__ __nv_bfloat16 g_hhi[2][BATCH * HID];
__device__ __nv_bfloat16 g_hlo[2][BATCH * HID];
__device__ float g_hf[BATCH * HID];
__device__ float g_c[BATCH * HID];

// ---------------------------------------------------------------------------
// sm_80-safe PTX helpers
// ---------------------------------------------------------------------------
__device__ __forceinline__ uint32_t smem_u32(const void* p) {
    return (uint32_t)__cvta_generic_to_shared(p);
}
__device__ __forceinline__ void cp_async16(uint32_t saddr, const void* gaddr) {
    asm volatile("cp.async.cg.shared.global [%0], [%1], 16;" ::
                 "r"(saddr), "l"(gaddr));
}
__device__ __forceinline__ void cp_commit() {
    asm volatile("cp.async.commit_group;");
}
__device__ __forceinline__ void cp_wait1() {
    asm volatile("cp.async.wait_group 1;");
}
__device__ __forceinline__ void cp_wait0() {
    asm volatile("cp.async.wait_group 0;");
}
__device__ __forceinline__ void bar_sync(int id, int nthreads) {
    asm volatile("bar.sync %0, %1;" :: "r"(id), "r"(nthreads) : "memory");
}
__device__ __forceinline__ void ldmx4(uint32_t addr, uint32_t* r) {
    asm volatile("ldmatrix.sync.aligned.m8n8.x4.shared.b16 {%0,%1,%2,%3}, [%4];"
                 : "=r"(r[0]), "=r"(r[1]), "=r"(r[2]), "=r"(r[3]) : "r"(addr));
}
__device__ __forceinline__ void mma_bf16(float* d, const uint32_t* a,
                                         uint32_t b0, uint32_t b1) {
    asm volatile(
        "mma.sync.aligned.m16n8k16.row.col.f32.bf16.bf16.f32 "
        "{%0,%1,%2,%3}, {%4,%5,%6,%7}, {%8,%9}, {%0,%1,%2,%3};"
        : "+f"(d[0]), "+f"(d[1]), "+f"(d[2]), "+f"(d[3])
        : "r"(a[0]), "r"(a[1]), "r"(a[2]), "r"(a[3]), "r"(b0), "r"(b1));
}

// ---------------------------------------------------------------------------
// Fused LSTM step via bf16-split HMMA, split-K dual warp-groups.
// CTA tile: M=128 ({4 gates} x {32 j}), N=64 batches. Grid (32, 4), 512 thr.
// Group g (8 warps) owns K-chunks [g*20, g*20+20), private stages
// [g*3, g*3+3), named barrier g+1, 3-stage distance-2 prefetch,
// ONE group barrier per chunk. Warp tile 32x32. Partials reduced via smem.
// ---------------------------------------------------------------------------
__global__ __launch_bounds__(512) void lstm_mma_step(
    const __nv_bfloat16* __restrict__ x_hi, const __nv_bfloat16* __restrict__ x_lo,
    const __nv_bfloat16* __restrict__ h_hi_in, const __nv_bfloat16* __restrict__ h_lo_in,
    float* __restrict__ h_out,
    __nv_bfloat16* __restrict__ h_hi_out, __nv_bfloat16* __restrict__ h_lo_out,
    float* __restrict__ c,
    const float* __restrict__ b_ih, const float* __restrict__ b_hh)
{
    extern __shared__ __align__(128) char sm[];
    const uint32_t smb = smem_u32(sm);

    const int tid = threadIdx.x;
    const int wid = tid >> 5;
    const int lane = tid & 31;
    const int grp = wid >> 3;          // warp-group 0/1
    const int wg = wid & 7;            // warp within group
    const int gtid = tid & 255;        // thread within group
    const int j0 = blockIdx.x * 32;
    const int b0 = blockIdx.y * 64;

    const int moff = (wg & 3) * 32;    // warp M offset (0..96)
    const int noff = (wg >> 2) * 32;   // warp N offset (0 or 32)

    float acc[2][4][4];
#pragma unroll
    for (int t = 0; t < 2; t++)
#pragma unroll
        for (int q = 0; q < 4; q++)
#pragma unroll
            for (int i = 0; i < 4; i++) acc[t][q][i] = 0.f;

    // ---------------- loader (cp.async, 6 x 16B per group thread) ---------
    auto issue_loads = [&](int chunk, int stage) {
        const __nv_bfloat16 *Ahi, *Alo, *Bhi, *Blo;
        int ks, k0;
        if (chunk < NCHUNK_H) {
            Ahi = g_Whh_hi; Alo = g_Whh_lo; Bhi = h_hi_in; Blo = h_lo_in;
            ks = HID; k0 = chunk * KC;
        } else {
            Ahi = g_Wih_hi; Alo = g_Wih_lo; Bhi = x_hi; Blo = x_lo;
            ks = KPAD; k0 = (chunk - NCHUNK_H) * KC;
        }
        const uint32_t sbase = smb + stage * STAGE_BYTES;
#pragma unroll
        for (int i = 0; i < 6; i++) {
            int o = gtid + i * 256;               // 0..1535
            const __nv_bfloat16* g;
            uint32_t soff;
            if (o < 1024) {                       // A: 128 rows x 4 chunks, hi+lo
                int m = o & 511;
                int r = m >> 2, c4 = m & 3;
                int grow = ((r >> 5) * HID) + j0 + (r & 31);
                g = ((o < 512) ? Ahi : Alo) + (size_t)grow * ks + k0 + c4 * 8;
                soff = ((o < 512) ? OFF_AHI : OFF_ALO) + r * AROW + c4 * 16;
            } else {                              // B: 64 rows x 4 chunks, hi+lo
                int m = o - 1024;
                int mm = m & 255;
                int r = mm >> 2, c4 = mm & 3;
                g = ((m < 256) ? Bhi : Blo) + (size_t)(b0 + r) * ks + k0 + c4 * 8;
                soff = ((m < 256) ? OFF_BHI : OFF_BLO) + r * AROW + c4 * 16;
            }
            cp_async16(sbase + soff, g);
        }
        cp_commit();
    };

    // ---------------- compute (2 x k16 per chunk, 32x32 warp tile) --------
    auto compute_chunk = [&](int stage) {
        const uint32_t ab = smb + stage * STAGE_BYTES;
#pragma unroll
        for (int kk = 0; kk < KC; kk += 16) {
            const int col = kk + ((lane >> 4) << 3);   // ldmatrix column (halfs)
            uint32_t a_hi[2][4], a_lo[2][4];
#pragma unroll
            for (int t = 0; t < 2; t++) {
                int row = moff + t * 16 + (lane & 15);
                ldmx4(ab + OFF_AHI + row * AROW + col * 2, a_hi[t]);
                ldmx4(ab + OFF_ALO + row * AROW + col * 2, a_lo[t]);
            }
            uint32_t b_hi[2][4], b_lo[2][4];
#pragma unroll
            for (int u = 0; u < 2; u++) {
                int row = noff + u * 16 + (lane & 15);
                ldmx4(ab + OFF_BHI + row * AROW + col * 2, b_hi[u]);
                ldmx4(ab + OFF_BLO + row * AROW + col * 2, b_lo[u]);
            }
#pragma unroll
            for (int t = 0; t < 2; t++)
#pragma unroll
                for (int q = 0; q < 4; q++) {
                    int u = q >> 1, v = q & 1;
                    mma_bf16(acc[t][q], a_hi[t], b_hi[u][v], b_hi[u][v + 2]);
                    mma_bf16(acc[t][q], a_hi[t], b_lo[u][v], b_lo[u][v + 2]);
                    mma_bf16(acc[t][q], a_lo[t], b_hi[u][v], b_hi[u][v + 2]);
                }
        }
    };

    // ---------------- per-group pipelined mainloop ------------------------
    // iter i: wait chunk i -> group barrier (licenses overwriting stage
    // (i-1)%3, read at iter i-1) -> prefetch chunk i+2 into that stage ->
    // compute chunk i. Distance 2 <= NSTAGE-1: no stage reuse hazard.
    {
        const int cbase = grp * NCHPG;
        const int sb = grp * NSTAGE;
        issue_loads(cbase + 0, sb + 0);
        issue_loads(cbase + 1, sb + 1);
        for (int i = 0; i < NCHPG; i++) {
            if (i + 1 < NCHPG) cp_wait1(); else cp_wait0();
            bar_sync(grp + 1, 256);
            if (i + 2 < NCHPG) issue_loads(cbase + i + 2, sb + (i + 2) % NSTAGE);
            compute_chunk(sb + i % NSTAGE);
        }
        // drain: all group warps finished all compute before Dsm overwrite
        bar_sync(grp + 1, 256);
    }

    // ---------------- epilogue: partials -> smem -> reduce -> pointwise ---
    float* Dsm = reinterpret_cast<float*>(sm + grp * GRP_BYTES);
#pragma unroll
    for (int t = 0; t < 2; t++)
#pragma unroll
        for (int q = 0; q < 4; q++) {
            int r0 = moff + t * 16 + (lane >> 2);
            int c0 = noff + q * 8 + (lane & 3) * 2;
            Dsm[r0 * 68 + c0]           = acc[t][q][0];
            Dsm[r0 * 68 + c0 + 1]       = acc[t][q][1];
            Dsm[(r0 + 8) * 68 + c0]     = acc[t][q][2];
            Dsm[(r0 + 8) * 68 + c0 + 1] = acc[t][q][3];
        }
    __syncthreads();

    const float* D1 = reinterpret_cast<const float*>(sm);
    const float* D2 = reinterpret_cast<const float*>(sm + GRP_BYTES);
#pragma unroll
    for (int i = 0; i < 4; i++) {
        int id = tid + i * 512;      // 0..2047
        int bb = id >> 5;            // 0..63
        int jj = id & 31;
        int b = b0 + bb;
        int jg = j0 + jj;
        float gi = D1[(0  + jj) * 68 + bb] + D2[(0  + jj) * 68 + bb] + b_ih[jg]         + b_hh[jg];
        float gf = D1[(32 + jj) * 68 + bb] + D2[(32 + jj) * 68 + bb] + b_ih[HID + jg]   + b_hh[HID + jg];
        float gg = D1[(64 + jj) * 68 + bb] + D2[(64 + jj) * 68 + bb] + b_ih[2*HID + jg] + b_hh[2*HID + jg];
        float go = D1[(96 + jj) * 68 + bb] + D2[(96 + jj) * 68 + bb] + b_ih[3*HID + jg] + b_hh[3*HID + jg];
        float iv = 1.f / (1.f + expf(-gi));
        float fv = 1.f / (1.f + expf(-gf));
        float gv = tanhf(gg);
        float ov = 1.f / (1.f + expf(-go));
        size_t idx = (size_t)b * HID + jg;
        float cn = fv * c[idx] + iv * gv;
        c[idx] = cn;
        float hv = ov * tanhf(cn);
        h_out[idx] = hv;
        __nv_bfloat16 hh = __float2bfloat16(hv);
        h_hi_out[idx] = hh;
        h_lo_out[idx] = __float2bfloat16(hv - __bfloat162float(hh));
    }
}

// ---------------------------------------------------------------------------
// Conversion kernels
// ---------------------------------------------------------------------------
__global__ void split_mat_kernel(const float* __restrict__ src,
                                 __nv_bfloat16* __restrict__ hi,
                                 __nv_bfloat16* __restrict__ lo, int n) {
    int i = blockIdx.x * blockDim.x + threadIdx.x;
    if (i < n) {
        float v = src[i];
        __nv_bfloat16 h = __float2bfloat16(v);
        hi[i] = h;
        lo[i] = __float2bfloat16(v - __bfloat162float(h));
    }
}

__global__ void split_pad_kernel(const float* __restrict__ src, int srcStride, int srcK,
                                 __nv_bfloat16* __restrict__ hi,
                                 __nv_bfloat16* __restrict__ lo, int rows, int dstK) {
    int i = blockIdx.x * blockDim.x + threadIdx.x;
    if (i < rows * dstK) {
        int r = i / dstK, k = i % dstK;
        float v = (k < srcK) ? src[(size_t)r * srcStride + k] : 0.f;
        __nv_bfloat16 h = __float2bfloat16(v);
        hi[i] = h;
        lo[i] = __float2bfloat16(v - __bfloat162float(h));
    }
}

__global__ void split_src_kernel(const float* __restrict__ src,
                                 __nv_bfloat16* __restrict__ hi,
                                 __nv_bfloat16* __restrict__ lo) {
    int i = blockIdx.x * blockDim.x + threadIdx.x;
    if (i < SRCLEN * BATCH * KPAD) {
        int k = i & (KPAD - 1);
        int sb = i >> 8;
        int b = sb & (BATCH - 1);
        int s = sb >> 8;
        float v = (k < DIN) ? src[((size_t)b * SRCLEN + s) * DIN + k] : 0.f;
        __nv_bfloat16 h = __float2bfloat16(v);
        hi[i] = h;
        lo[i] = __float2bfloat16(v - __bfloat162float(h));
    }
}

// ---------------------------------------------------------------------------
// Output projection fused with feedback split:
// out[b,d] = h[b,:] @ W_out[d,:] + b_out[d]; also writes xd hi/lo (d < DIN).
// ---------------------------------------------------------------------------
__global__ __launch_bounds__(256) void out_proj_kernel(
    const float* __restrict__ h,
    const float* __restrict__ W_out,
    const float* __restrict__ b_out,
    float* __restrict__ out, int out_stride,
    __nv_bfloat16* __restrict__ xd_hi, __nv_bfloat16* __restrict__ xd_lo)
{
    __shared__ float Hs[16][17];
    __shared__ float Wo[16][17];

    const int tid = threadIdx.x;
    const int txd = tid & 15;
    const int tyb = tid >> 4;
    const int d0 = blockIdx.x * 16;
    const int b0 = blockIdx.y * 16;

    float acc = 0.f;
    for (int k0 = 0; k0 < HID; k0 += 16) {
        __syncthreads();
        Hs[txd][tyb] = h[(size_t)(b0 + tyb) * HID + k0 + txd];
        Wo[txd][tyb] = (d0 + tyb < DIN)
            ? W_out[(size_t)(d0 + tyb) * HID + k0 + txd] : 0.f;
        __syncthreads();
#pragma unroll
        for (int k = 0; k < 16; k++)
            acc += Hs[k][tyb] * Wo[k][txd];
    }
    if (d0 + txd < DIN) {
        float v = acc + b_out[d0 + txd];
        out[(size_t)(b0 + tyb) * out_stride + d0 + txd] = v;
        if (xd_hi) {
            size_t xi = (size_t)(b0 + tyb) * KPAD + d0 + txd;
            __nv_bfloat16 hh = __float2bfloat16(v);
            xd_hi[xi] = hh;
            xd_lo[xi] = __float2bfloat16(v - __bfloat162float(hh));
        }
    }
}

// ---------------------------------------------------------------------------
extern "C" void kernel_launch(void* const* d_in, const int* in_sizes, int n_in,
                              void* d_out, int out_size)
{
    const float* src   = (const float*)d_in[0];
    const float* W_ih  = (const float*)d_in[2];
    const float* W_hh  = (const float*)d_in[3];
    const float* b_ih  = (const float*)d_in[4];
    const float* b_hh  = (const float*)d_in[5];
    const float* W_out = (const float*)d_in[6];
    const float* b_out = (const float*)d_in[7];
    float* out = (float*)d_out;

    static bool attr_set = false;
    if (!attr_set) {
        cudaFuncSetAttribute(lstm_mma_step,
                             cudaFuncAttributeMaxDynamicSharedMemorySize, SMEM_TOTAL);
        attr_set = true;
    }

    __nv_bfloat16 *Whh_hi, *Wih_hi, *Xs_hi, *Xs_lo, *xd_hi, *xd_lo, *hhi, *hlo;
    __nv_bfloat16 *Whh_lo, *Wih_lo;
    float *hf, *cc;
    cudaGetSymbolAddress((void**)&Whh_hi, g_Whh_hi);
    cudaGetSymbolAddress((void**)&Whh_lo, g_Whh_lo);
    cudaGetSymbolAddress((void**)&Wih_hi, g_Wih_hi);
    cudaGetSymbolAddress((void**)&Wih_lo, g_Wih_lo);
    cudaGetSymbolAddress((void**)&Xs_hi, g_Xsrc_hi);
    cudaGetSymbolAddress((void**)&Xs_lo, g_Xsrc_lo);
    cudaGetSymbolAddress((void**)&xd_hi, g_xdec_hi);
    cudaGetSymbolAddress((void**)&xd_lo, g_xdec_lo);
    cudaGetSymbolAddress((void**)&hhi, g_hhi);
    cudaGetSymbolAddress((void**)&hlo, g_hlo);
    cudaGetSymbolAddress((void**)&hf, g_hf);
    cudaGetSymbolAddress((void**)&cc, g_c);
    __nv_bfloat16* hhb[2] = {hhi, hhi + BATCH * HID};
    __nv_bfloat16* hlb[2] = {hlo, hlo + BATCH * HID};

    cudaMemsetAsync(hhb[0], 0, (size_t)BATCH * HID * sizeof(__nv_bfloat16));
    cudaMemsetAsync(hlb[0], 0, (size_t)BATCH * HID * sizeof(__nv_bfloat16));
    cudaMemsetAsync(cc, 0, (size_t)BATCH * HID * sizeof(float));
    cudaMemsetAsync(xd_hi, 0, (size_t)BATCH * KPAD * sizeof(__nv_bfloat16));
    cudaMemsetAsync(xd_lo, 0, (size_t)BATCH * KPAD * sizeof(__nv_bfloat16));

    {
        int n = 4096 * HID;
        split_mat_kernel<<<(n + 255) / 256, 256>>>(W_hh, Whh_hi, Whh_lo, n);
        split_pad_kernel<<<(4096 * KPAD + 255) / 256, 256>>>(W_ih, DIN, DIN,
                                                             Wih_hi, Wih_lo, 4096, KPAD);
        int m = SRCLEN * BATCH * KPAD;
        split_src_kernel<<<(m + 255) / 256, 256>>>(src, Xs_hi, Xs_lo);
    }

    dim3 grid(32, 4);
    dim3 pgrid(14, 16);
    int cur = 0;

    // Encoder
    for (int s = 0; s < SRCLEN; s++) {
        lstm_mma_step<<<grid, 512, SMEM_TOTAL>>>(
            Xs_hi + (size_t)s * BATCH * KPAD, Xs_lo + (size_t)s * BATCH * KPAD,
            hhb[cur], hlb[cur], hf, hhb[1 - cur], hlb[1 - cur], cc, b_ih, b_hh);
        cur ^= 1;
    }

    // Decoder
    const __nv_bfloat16* x_hi = Xs_hi + (size_t)(SRCLEN - 1) * BATCH * KPAD;
    const __nv_bfloat16* x_lo = Xs_lo + (size_t)(SRCLEN - 1) * BATCH * KPAD;
    for (int t = 0; t < TGTLEN; t++) {
        lstm_mma_step<<<grid, 512, SMEM_TOTAL>>>(
            x_hi, x_lo, hhb[cur], hlb[cur], hf, hhb[1 - cur], hlb[1 - cur],
            cc, b_ih, b_hh);
        cur ^= 1;
        bool feed = (t + 1 < TGTLEN);
        out_proj_kernel<<<pgrid, 256>>>(hf, W_out, b_out,
                                        out + (size_t)t * DIN, TGTLEN * DIN,
                                        feed ? xd_hi : nullptr,
                                        feed ? xd_lo : nullptr);
        x_hi = xd_hi;
        x_lo = xd_lo;
    }
}

// round 9
// speedup vs baseline: 1.0676x; 1.0676x over previous
#include <cuda_runtime.h>
#include <cuda_bf16.h>
#include <cstdint>
#include <math.h>

#define BATCH 256
#define SRCLEN 120
#define TGTLEN 24
#define DIN 216
#define HID 1024
#define KPAD 256

#define KC 64                 // K per pipeline chunk
#define NCHUNK_H (HID / KC)   // 16
#define NCHUNK_X (KPAD / KC)  // 4
#define NCHUNK (NCHUNK_H + NCHUNK_X)
#define NSTAGE 3

#define AROW 144              // smem row stride bytes (128B data + 16B pad)
#define OFF_AHI 0
#define OFF_ALO 18432
#define OFF_BHI 36864
#define OFF_BLO 46080
#define STAGE_BYTES 55296
#define SMEM_TOTAL (NSTAGE * STAGE_BYTES)

// ---------------------------------------------------------------------------
// Static device scratch (no runtime allocation allowed)
// ---------------------------------------------------------------------------
__device__ __nv_bfloat16 g_Whh_hi[4096 * HID];
__device__ __nv_bfloat16 g_Whh_lo[4096 * HID];
__device__ __nv_bfloat16 g_Wih_hi[4096 * KPAD];
__device__ __nv_bfloat16 g_Wih_lo[4096 * KPAD];
__device__ __nv_bfloat16 g_Xsrc_hi[SRCLEN * BATCH * KPAD];
__device__ __nv_bfloat16 g_Xsrc_lo[SRCLEN * BATCH * KPAD];
__device__ __nv_bfloat16 g_xdec_hi[BATCH * KPAD];
__device__ __nv_bfloat16 g_xdec_lo[BATCH * KPAD];
__device__ __nv_bfloat16 g_hhi[2][BATCH * HID];
__device__ __nv_bfloat16 g_hlo[2][BATCH * HID];
__device__ float g_hf[BATCH * HID];
__device__ float g_c[BATCH * HID];

// ---------------------------------------------------------------------------
// sm_80-safe PTX helpers
// ---------------------------------------------------------------------------
__device__ __forceinline__ uint32_t smem_u32(const void* p) {
    return (uint32_t)__cvta_generic_to_shared(p);
}
__device__ __forceinline__ void cp_async16(uint32_t saddr, const void* gaddr) {
    asm volatile("cp.async.cg.shared.global [%0], [%1], 16;" ::
                 "r"(saddr), "l"(gaddr));
}
__device__ __forceinline__ void cp_commit() {
    asm volatile("cp.async.commit_group;");
}
__device__ __forceinline__ void cp_wait1() {
    asm volatile("cp.async.wait_group 1;");
}
__device__ __forceinline__ void cp_wait0() {
    asm volatile("cp.async.wait_group 0;");
}
__device__ __forceinline__ void ldmx4(uint32_t addr, uint32_t* r) {
    asm volatile("ldmatrix.sync.aligned.m8n8.x4.shared.b16 {%0,%1,%2,%3}, [%4];"
                 : "=r"(r[0]), "=r"(r[1]), "=r"(r[2]), "=r"(r[3]) : "r"(addr));
}
__device__ __forceinline__ void mma_bf16(float* d, const uint32_t* a,
                                         uint32_t b0, uint32_t b1) {
    asm volatile(
        "mma.sync.aligned.m16n8k16.row.col.f32.bf16.bf16.f32 "
        "{%0,%1,%2,%3}, {%4,%5,%6,%7}, {%8,%9}, {%0,%1,%2,%3};"
        : "+f"(d[0]), "+f"(d[1]), "+f"(d[2]), "+f"(d[3])
        : "r"(a[0]), "r"(a[1]), "r"(a[2]), "r"(a[3]), "r"(b0), "r"(b1));
}

// ---------------------------------------------------------------------------
// Fused LSTM step via bf16-split HMMA.
// CTA tile: M=128 ({4 gates} x {32 j}), N=64 batches. Grid (32, 4), 512 thr.
// 16 warps, warp tile 32x16. KC=64 chunks, 3-stage cp.async pipe,
// 1 barrier/chunk. Warp-staggered k16 order (de-lockstep LDSM vs MMA) and
// per-split-term accumulators (independent MMA chains).
// ---------------------------------------------------------------------------
__global__ __launch_bounds__(512) void lstm_mma_step(
    const __nv_bfloat16* __restrict__ x_hi, const __nv_bfloat16* __restrict__ x_lo,
    const __nv_bfloat16* __restrict__ h_hi_in, const __nv_bfloat16* __restrict__ h_lo_in,
    float* __restrict__ h_out,
    __nv_bfloat16* __restrict__ h_hi_out, __nv_bfloat16* __restrict__ h_lo_out,
    float* __restrict__ c,
    const float* __restrict__ b_ih, const float* __restrict__ b_hh)
{
    extern __shared__ __align__(128) char sm[];
    const uint32_t smb = smem_u32(sm);

    const int tid = threadIdx.x;
    const int wid = tid >> 5;
    const int lane = tid & 31;
    const int j0 = blockIdx.x * 32;
    const int b0 = blockIdx.y * 64;

    const int moff = (wid & 3) * 32;   // warp M offset (0..96)
    const int noff = (wid >> 2) * 16;  // warp N offset (0,16,32,48)
    const int rot = wid & 3;           // per-warp k16-group rotation

    float acc0[2][2][4], acc1[2][2][4], acc2[2][2][4];
#pragma unroll
    for (int t = 0; t < 2; t++)
#pragma unroll
        for (int q = 0; q < 2; q++)
#pragma unroll
            for (int i = 0; i < 4; i++) {
                acc0[t][q][i] = 0.f;
                acc1[t][q][i] = 0.f;
                acc2[t][q][i] = 0.f;
            }

    // ---------------- loader (cp.async, 6 x 16B per thread) ---------------
    auto issue_loads = [&](int chunk, int stage) {
        const __nv_bfloat16 *Ahi, *Alo, *Bhi, *Blo;
        int ks, k0;
        if (chunk < NCHUNK_H) {
            Ahi = g_Whh_hi; Alo = g_Whh_lo; Bhi = h_hi_in; Blo = h_lo_in;
            ks = HID; k0 = chunk * KC;
        } else {
            Ahi = g_Wih_hi; Alo = g_Wih_lo; Bhi = x_hi; Blo = x_lo;
            ks = KPAD; k0 = (chunk - NCHUNK_H) * KC;
        }
        const uint32_t sbase = smb + stage * STAGE_BYTES;
#pragma unroll
        for (int i = 0; i < 6; i++) {
            int o = tid + i * 512;                // 0..3071
            const __nv_bfloat16* g;
            uint32_t soff;
            if (o < 2048) {                       // A: 128 rows x 8 chunks, hi+lo
                int m = o & 1023;
                int r = m >> 3, c8 = m & 7;
                int grow = ((r >> 5) * HID) + j0 + (r & 31);
                g = ((o < 1024) ? Ahi : Alo) + (size_t)grow * ks + k0 + c8 * 8;
                soff = ((o < 1024) ? OFF_AHI : OFF_ALO) + r * AROW + c8 * 16;
            } else {                              // B: 64 rows x 8 chunks, hi+lo
                int m = o - 2048;
                int mm = m & 511;
                int r = mm >> 3, c8 = mm & 7;
                g = ((m < 512) ? Bhi : Blo) + (size_t)(b0 + r) * ks + k0 + c8 * 8;
                soff = ((m < 512) ? OFF_BHI : OFF_BLO) + r * AROW + c8 * 16;
            }
            cp_async16(sbase + soff, g);
        }
        cp_commit();
    };

    // ---------------- compute (4 x k16, warp-rotated order) ---------------
    auto compute_chunk = [&](int stage) {
        const uint32_t ab = smb + stage * STAGE_BYTES;
#pragma unroll
        for (int g = 0; g < 4; g++) {
            const int kk = ((g + rot) & 3) * 16;
            const int col = kk + ((lane >> 4) << 3);   // ldmatrix column (halfs)
            uint32_t a_hi[2][4], a_lo[2][4];
#pragma unroll
            for (int t = 0; t < 2; t++) {
                int row = moff + t * 16 + (lane & 15);
                ldmx4(ab + OFF_AHI + row * AROW + col * 2, a_hi[t]);
                ldmx4(ab + OFF_ALO + row * AROW + col * 2, a_lo[t]);
            }
            uint32_t b_hi[4], b_lo[4];
            {
                int row = noff + (lane & 15);
                ldmx4(ab + OFF_BHI + row * AROW + col * 2, b_hi);
                ldmx4(ab + OFF_BLO + row * AROW + col * 2, b_lo);
            }
#pragma unroll
            for (int t = 0; t < 2; t++)
#pragma unroll
                for (int q = 0; q < 2; q++) {
                    mma_bf16(acc0[t][q], a_hi[t], b_hi[q], b_hi[q + 2]);
                    mma_bf16(acc1[t][q], a_hi[t], b_lo[q], b_lo[q + 2]);
                    mma_bf16(acc2[t][q], a_lo[t], b_hi[q], b_hi[q + 2]);
                }
        }
    };

    // ---------------- pipelined mainloop: ONE barrier per chunk -----------
    issue_loads(0, 0);
    issue_loads(1, 1);
    for (int i = 0; i < NCHUNK; i++) {
        if (i + 1 < NCHUNK) cp_wait1(); else cp_wait0();
        __syncthreads();
        if (i + 2 < NCHUNK) issue_loads(i + 2, (i + 2) % NSTAGE);
        compute_chunk(i % NSTAGE);
    }

    // ---------------- epilogue: frags -> smem -> LSTM pointwise -----------
    float* Dsm = reinterpret_cast<float*>(sm);    // [128][68] stride
#pragma unroll
    for (int t = 0; t < 2; t++)
#pragma unroll
        for (int q = 0; q < 2; q++) {
            int r0 = moff + t * 16 + (lane >> 2);
            int c0 = noff + q * 8 + (lane & 3) * 2;
#pragma unroll
            for (int i = 0; i < 4; i++) {
                float v = acc0[t][q][i] + acc1[t][q][i] + acc2[t][q][i];
                int rr = r0 + (i >> 1) * 8;
                int cc = c0 + (i & 1);
                Dsm[rr * 68 + cc] = v;
            }
        }
    __syncthreads();

#pragma unroll
    for (int i = 0; i < 4; i++) {
        int id = tid + i * 512;      // 0..2047
        int bb = id >> 5;            // 0..63
        int jj = id & 31;
        int b = b0 + bb;
        int jg = j0 + jj;
        float gi = Dsm[(0   + jj) * 68 + bb] + b_ih[jg]           + b_hh[jg];
        float gf = Dsm[(32  + jj) * 68 + bb] + b_ih[HID + jg]     + b_hh[HID + jg];
        float gg = Dsm[(64  + jj) * 68 + bb] + b_ih[2*HID + jg]   + b_hh[2*HID + jg];
        float go = Dsm[(96  + jj) * 68 + bb] + b_ih[3*HID + jg]   + b_hh[3*HID + jg];
        float iv = 1.f / (1.f + expf(-gi));
        float fv = 1.f / (1.f + expf(-gf));
        float gv = tanhf(gg);
        float ov = 1.f / (1.f + expf(-go));
        size_t idx = (size_t)b * HID + jg;
        float cn = fv * c[idx] + iv * gv;
        c[idx] = cn;
        float hv = ov * tanhf(cn);
        h_out[idx] = hv;
        __nv_bfloat16 hh = __float2bfloat16(hv);
        h_hi_out[idx] = hh;
        h_lo_out[idx] = __float2bfloat16(hv - __bfloat162float(hh));
    }
}

// ---------------------------------------------------------------------------
// Conversion kernels
// ---------------------------------------------------------------------------
__global__ void split_mat_kernel(const float* __restrict__ src,
                                 __nv_bfloat16* __restrict__ hi,
                                 __nv_bfloat16* __restrict__ lo, int n) {
    int i = blockIdx.x * blockDim.x + threadIdx.x;
    if (i < n) {
        float v = src[i];
        __nv_bfloat16 h = __float2bfloat16(v);
        hi[i] = h;
        lo[i] = __float2bfloat16(v - __bfloat162float(h));
    }
}

__global__ void split_pad_kernel(const float* __restrict__ src, int srcStride, int srcK,
                                 __nv_bfloat16* __restrict__ hi,
                                 __nv_bfloat16* __restrict__ lo, int rows, int dstK) {
    int i = blockIdx.x * blockDim.x + threadIdx.x;
    if (i < rows * dstK) {
        int r = i / dstK, k = i % dstK;
        float v = (k < srcK) ? src[(size_t)r * srcStride + k] : 0.f;
        __nv_bfloat16 h = __float2bfloat16(v);
        hi[i] = h;
        lo[i] = __float2bfloat16(v - __bfloat162float(h));
    }
}

__global__ void split_src_kernel(const float* __restrict__ src,
                                 __nv_bfloat16* __restrict__ hi,
                                 __nv_bfloat16* __restrict__ lo) {
    int i = blockIdx.x * blockDim.x + threadIdx.x;
    if (i < SRCLEN * BATCH * KPAD) {
        int k = i & (KPAD - 1);
        int sb = i >> 8;
        int b = sb & (BATCH - 1);
        int s = sb >> 8;
        float v = (k < DIN) ? src[((size_t)b * SRCLEN + s) * DIN + k] : 0.f;
        __nv_bfloat16 h = __float2bfloat16(v);
        hi[i] = h;
        lo[i] = __float2bfloat16(v - __bfloat162float(h));
    }
}

// ---------------------------------------------------------------------------
// Output projection fused with feedback split:
// out[b,d] = h[b,:] @ W_out[d,:] + b_out[d]; also writes xd hi/lo (d < DIN).
// ---------------------------------------------------------------------------
__global__ __launch_bounds__(256) void out_proj_kernel(
    const float* __restrict__ h,
    const float* __restrict__ W_out,
    const float* __restrict__ b_out,
    float* __restrict__ out, int out_stride,
    __nv_bfloat16* __restrict__ xd_hi, __nv_bfloat16* __restrict__ xd_lo)
{
    __shared__ float Hs[16][17];
    __shared__ float Wo[16][17];

    const int tid = threadIdx.x;
    const int txd = tid & 15;
    const int tyb = tid >> 4;
    const int d0 = blockIdx.x * 16;
    const int b0 = blockIdx.y * 16;

    float acc = 0.f;
    for (int k0 = 0; k0 < HID; k0 += 16) {
        __syncthreads();
        Hs[txd][tyb] = h[(size_t)(b0 + tyb) * HID + k0 + txd];
        Wo[txd][tyb] = (d0 + tyb < DIN)
            ? W_out[(size_t)(d0 + tyb) * HID + k0 + txd] : 0.f;
        __syncthreads();
#pragma unroll
        for (int k = 0; k < 16; k++)
            acc += Hs[k][tyb] * Wo[k][txd];
    }
    if (d0 + txd < DIN) {
        float v = acc + b_out[d0 + txd];
        out[(size_t)(b0 + tyb) * out_stride + d0 + txd] = v;
        if (xd_hi) {
            size_t xi = (size_t)(b0 + tyb) * KPAD + d0 + txd;
            __nv_bfloat16 hh = __float2bfloat16(v);
            xd_hi[xi] = hh;
            xd_lo[xi] = __float2bfloat16(v - __bfloat162float(hh));
        }
    }
}

// ---------------------------------------------------------------------------
extern "C" void kernel_launch(void* const* d_in, const int* in_sizes, int n_in,
                              void* d_out, int out_size)
{
    const float* src   = (const float*)d_in[0];
    const float* W_ih  = (const float*)d_in[2];
    const float* W_hh  = (const float*)d_in[3];
    const float* b_ih  = (const float*)d_in[4];
    const float* b_hh  = (const float*)d_in[5];
    const float* W_out = (const float*)d_in[6];
    const float* b_out = (const float*)d_in[7];
    float* out = (float*)d_out;

    static bool attr_set = false;
    if (!attr_set) {
        cudaFuncSetAttribute(lstm_mma_step,
                             cudaFuncAttributeMaxDynamicSharedMemorySize, SMEM_TOTAL);
        attr_set = true;
    }

    __nv_bfloat16 *Whh_hi, *Wih_hi, *Xs_hi, *Xs_lo, *xd_hi, *xd_lo, *hhi, *hlo;
    __nv_bfloat16 *Whh_lo, *Wih_lo;
    float *hf, *cc;
    cudaGetSymbolAddress((void**)&Whh_hi, g_Whh_hi);
    cudaGetSymbolAddress((void**)&Whh_lo, g_Whh_lo);
    cudaGetSymbolAddress((void**)&Wih_hi, g_Wih_hi);
    cudaGetSymbolAddress((void**)&Wih_lo, g_Wih_lo);
    cudaGetSymbolAddress((void**)&Xs_hi, g_Xsrc_hi);
    cudaGetSymbolAddress((void**)&Xs_lo, g_Xsrc_lo);
    cudaGetSymbolAddress((void**)&xd_hi, g_xdec_hi);
    cudaGetSymbolAddress((void**)&xd_lo, g_xdec_lo);
    cudaGetSymbolAddress((void**)&hhi, g_hhi);
    cudaGetSymbolAddress((void**)&hlo, g_hlo);
    cudaGetSymbolAddress((void**)&hf, g_hf);
    cudaGetSymbolAddress((void**)&cc, g_c);
    __nv_bfloat16* hhb[2] = {hhi, hhi + BATCH * HID};
    __nv_bfloat16* hlb[2] = {hlo, hlo + BATCH * HID};

    cudaMemsetAsync(hhb[0], 0, (size_t)BATCH * HID * sizeof(__nv_bfloat16));
    cudaMemsetAsync(hlb[0], 0, (size_t)BATCH * HID * sizeof(__nv_bfloat16));
    cudaMemsetAsync(cc, 0, (size_t)BATCH * HID * sizeof(float));
    cudaMemsetAsync(xd_hi, 0, (size_t)BATCH * KPAD * sizeof(__nv_bfloat16));
    cudaMemsetAsync(xd_lo, 0, (size_t)BATCH * KPAD * sizeof(__nv_bfloat16));

    {
        int n = 4096 * HID;
        split_mat_kernel<<<(n + 255) / 256, 256>>>(W_hh, Whh_hi, Whh_lo, n);
        split_pad_kernel<<<(4096 * KPAD + 255) / 256, 256>>>(W_ih, DIN, DIN,
                                                             Wih_hi, Wih_lo, 4096, KPAD);
        int m = SRCLEN * BATCH * KPAD;
        split_src_kernel<<<(m + 255) / 256, 256>>>(src, Xs_hi, Xs_lo);
    }

    dim3 grid(32, 4);
    dim3 pgrid(14, 16);
    int cur = 0;

    // Encoder
    for (int s = 0; s < SRCLEN; s++) {
        lstm_mma_step<<<grid, 512, SMEM_TOTAL>>>(
            Xs_hi + (size_t)s * BATCH * KPAD, Xs_lo + (size_t)s * BATCH * KPAD,
            hhb[cur], hlb[cur], hf, hhb[1 - cur], hlb[1 - cur], cc, b_ih, b_hh);
        cur ^= 1;
    }

    // Decoder
    const __nv_bfloat16* x_hi = Xs_hi + (size_t)(SRCLEN - 1) * BATCH * KPAD;
    const __nv_bfloat16* x_lo = Xs_lo + (size_t)(SRCLEN - 1) * BATCH * KPAD;
    for (int t = 0; t < TGTLEN; t++) {
        lstm_mma_step<<<grid, 512, SMEM_TOTAL>>>(
            x_hi, x_lo, hhb[cur], hlb[cur], hf, hhb[1 - cur], hlb[1 - cur],
            cc, b_ih, b_hh);
        cur ^= 1;
        bool feed = (t + 1 < TGTLEN);
        out_proj_kernel<<<pgrid, 256>>>(hf, W_out, b_out,
                                        out + (size_t)t * DIN, TGTLEN * DIN,
                                        feed ? xd_hi : nullptr,
                                        feed ? xd_lo : nullptr);
        x_hi = xd_hi;
        x_lo = xd_lo;
    }
}

// round 11
// speedup vs baseline: 1.1054x; 1.0354x over previous
#include <cuda_runtime.h>
#include <cuda_bf16.h>
#include <cstdint>
#include <math.h>

#define BATCH 256
#define SRCLEN 120
#define TGTLEN 24
#define DIN 216
#define HID 1024
#define KPAD 256

#define KC 128                // K per pipeline chunk
#define NCHUNK_H (HID / KC)   // 8
#define NCHUNK_X (KPAD / KC)  // 2
#define NCHUNK (NCHUNK_H + NCHUNK_X)   // 10
#define NSTAGE 2

#define AROW 272              // smem row stride bytes (256B data + 16B pad)
#define OFF_AHI 0
#define OFF_ALO 34816
#define OFF_BHI 69632
#define OFF_BLO 87040
#define STAGE_BYTES 104448
#define SMEM_TOTAL (NSTAGE * STAGE_BYTES)   // 208896

// ---------------------------------------------------------------------------
// Static device scratch (no runtime allocation allowed)
// ---------------------------------------------------------------------------
__device__ __nv_bfloat16 g_Whh_hi[4096 * HID];
__device__ __nv_bfloat16 g_Whh_lo[4096 * HID];
__device__ __nv_bfloat16 g_Wih_hi[4096 * KPAD];
__device__ __nv_bfloat16 g_Wih_lo[4096 * KPAD];
__device__ __nv_bfloat16 g_Xsrc_hi[SRCLEN * BATCH * KPAD];
__device__ __nv_bfloat16 g_Xsrc_lo[SRCLEN * BATCH * KPAD];
__device__ __nv_bfloat16 g_xdec_hi[BATCH * KPAD];
__device__ __nv_bfloat16 g_xdec_lo[BATCH * KPAD];
__device__ __nv_bfloat16 g_hhi[2][BATCH * HID];
__device__ __nv_bfloat16 g_hlo[2][BATCH * HID];
__device__ float g_hf[BATCH * HID];
__device__ float g_c[BATCH * HID];

// ---------------------------------------------------------------------------
// sm_80-safe PTX helpers
// ---------------------------------------------------------------------------
__device__ __forceinline__ uint32_t smem_u32(const void* p) {
    return (uint32_t)__cvta_generic_to_shared(p);
}
__device__ __forceinline__ void cp_async16(uint32_t saddr, const void* gaddr) {
    asm volatile("cp.async.cg.shared.global [%0], [%1], 16;" ::
                 "r"(saddr), "l"(gaddr));
}
__device__ __forceinline__ void cp_commit() {
    asm volatile("cp.async.commit_group;");
}
__device__ __forceinline__ void cp_wait0() {
    asm volatile("cp.async.wait_group 0;");
}
__device__ __forceinline__ void ldmx4(uint32_t addr, uint32_t* r) {
    asm volatile("ldmatrix.sync.aligned.m8n8.x4.shared.b16 {%0,%1,%2,%3}, [%4];"
                 : "=r"(r[0]), "=r"(r[1]), "=r"(r[2]), "=r"(r[3]) : "r"(addr));
}
__device__ __forceinline__ void mma_bf16(float* d, const uint32_t* a,
                                         uint32_t b0, uint32_t b1) {
    asm volatile(
        "mma.sync.aligned.m16n8k16.row.col.f32.bf16.bf16.f32 "
        "{%0,%1,%2,%3}, {%4,%5,%6,%7}, {%8,%9}, {%0,%1,%2,%3};"
        : "+f"(d[0]), "+f"(d[1]), "+f"(d[2]), "+f"(d[3])
        : "r"(a[0]), "r"(a[1]), "r"(a[2]), "r"(a[3]), "r"(b0), "r"(b1));
}

// ---------------------------------------------------------------------------
// Fused LSTM step via bf16-split HMMA.
// CTA tile: M=128 ({4 gates} x {32 j}), N=64 batches. Grid (32, 4), 512 thr.
// 16 warps, warp tile 32x16. KC=128, 2 stages, distance-1 prefetch.
// Loop order (CORRECT): cp_wait0 -> barrier (publishes chunk i writes AND
// licenses overwriting stage (i-1)&1) -> issue(i+1) -> compute(i).
// Warp-staggered k16 order + per-split-term accumulators.
// ---------------------------------------------------------------------------
__global__ __launch_bounds__(512) void lstm_mma_step(
    const __nv_bfloat16* __restrict__ x_hi, const __nv_bfloat16* __restrict__ x_lo,
    const __nv_bfloat16* __restrict__ h_hi_in, const __nv_bfloat16* __restrict__ h_lo_in,
    float* __restrict__ h_out,
    __nv_bfloat16* __restrict__ h_hi_out, __nv_bfloat16* __restrict__ h_lo_out,
    float* __restrict__ c,
    const float* __restrict__ b_ih, const float* __restrict__ b_hh)
{
    extern __shared__ __align__(128) char sm[];
    const uint32_t smb = smem_u32(sm);

    const int tid = threadIdx.x;
    const int wid = tid >> 5;
    const int lane = tid & 31;
    const int j0 = blockIdx.x * 32;
    const int b0 = blockIdx.y * 64;

    const int moff = (wid & 3) * 32;   // warp M offset (0..96)
    const int noff = (wid >> 2) * 16;  // warp N offset (0,16,32,48)
    const int rot = ((wid >> 2) + (wid & 3) * 4) & 7;  // k16-group rotation

    float acc0[2][2][4], acc1[2][2][4], acc2[2][2][4];
#pragma unroll
    for (int t = 0; t < 2; t++)
#pragma unroll
        for (int q = 0; q < 2; q++)
#pragma unroll
            for (int i = 0; i < 4; i++) {
                acc0[t][q][i] = 0.f;
                acc1[t][q][i] = 0.f;
                acc2[t][q][i] = 0.f;
            }

    // ---------------- loader (cp.async, 12 x 16B per thread) --------------
    auto issue_loads = [&](int chunk, int stage) {
        const __nv_bfloat16 *Ahi, *Alo, *Bhi, *Blo;
        int ks, k0;
        if (chunk < NCHUNK_H) {
            Ahi = g_Whh_hi; Alo = g_Whh_lo; Bhi = h_hi_in; Blo = h_lo_in;
            ks = HID; k0 = chunk * KC;
        } else {
            Ahi = g_Wih_hi; Alo = g_Wih_lo; Bhi = x_hi; Blo = x_lo;
            ks = KPAD; k0 = (chunk - NCHUNK_H) * KC;
        }
        const uint32_t sbase = smb + stage * STAGE_BYTES;
#pragma unroll
        for (int i = 0; i < 12; i++) {
            int o = tid + i * 512;                // 0..6143
            const __nv_bfloat16* g;
            uint32_t soff;
            if (o < 4096) {                       // A: 128 rows x 16 c16, hi+lo
                int m = o & 2047;
                int r = m >> 4, c16 = m & 15;
                int grow = ((r >> 5) * HID) + j0 + (r & 31);
                g = ((o < 2048) ? Ahi : Alo) + (size_t)grow * ks + k0 + c16 * 8;
                soff = ((o < 2048) ? OFF_AHI : OFF_ALO) + r * AROW + c16 * 16;
            } else {                              // B: 64 rows x 16 c16, hi+lo
                int m = o - 4096;
                int mm = m & 1023;
                int r = mm >> 4, c16 = mm & 15;
                g = ((m < 1024) ? Bhi : Blo) + (size_t)(b0 + r) * ks + k0 + c16 * 8;
                soff = ((m < 1024) ? OFF_BHI : OFF_BLO) + r * AROW + c16 * 16;
            }
            cp_async16(sbase + soff, g);
        }
        cp_commit();
    };

    // ---------------- compute (8 x k16, warp-rotated order) ---------------
    auto compute_chunk = [&](int stage) {
        const uint32_t ab = smb + stage * STAGE_BYTES;
#pragma unroll
        for (int g = 0; g < 8; g++) {
            const int kk = ((g + rot) & 7) * 16;
            const int col = kk + ((lane >> 4) << 3);   // ldmatrix column (halfs)
            uint32_t a_hi[2][4], a_lo[2][4];
#pragma unroll
            for (int t = 0; t < 2; t++) {
                int row = moff + t * 16 + (lane & 15);
                ldmx4(ab + OFF_AHI + row * AROW + col * 2, a_hi[t]);
                ldmx4(ab + OFF_ALO + row * AROW + col * 2, a_lo[t]);
            }
            uint32_t b_hi[4], b_lo[4];
            {
                int row = noff + (lane & 15);
                ldmx4(ab + OFF_BHI + row * AROW + col * 2, b_hi);
                ldmx4(ab + OFF_BLO + row * AROW + col * 2, b_lo);
            }
#pragma unroll
            for (int t = 0; t < 2; t++)
#pragma unroll
                for (int q = 0; q < 2; q++) {
                    mma_bf16(acc0[t][q], a_hi[t], b_hi[q], b_hi[q + 2]);
                    mma_bf16(acc1[t][q], a_hi[t], b_lo[q], b_lo[q + 2]);
                    mma_bf16(acc2[t][q], a_lo[t], b_hi[q], b_hi[q + 2]);
                }
        }
    };

    // ---------------- 2-stage, distance-1, ONE barrier per chunk ----------
    // iter i: cp_wait0 (own-thread chunk i done; it's the only pending
    // group) -> __syncthreads (publishes ALL threads' chunk-i writes, and
    // proves compute(i-1) done in every warp -> licenses overwriting stage
    // (i-1)&1) -> issue(i+1 -> stage (i+1)&1 == (i-1)&1) -> compute(i).
    issue_loads(0, 0);
    for (int i = 0; i < NCHUNK; i++) {
        cp_wait0();
        __syncthreads();
        if (i + 1 < NCHUNK) issue_loads(i + 1, (i + 1) & 1);
        compute_chunk(i & 1);
    }

    // ---------------- epilogue: frags -> smem -> LSTM pointwise -----------
    // Dsm (34.8KB) = stage-0 A_HI region. Last compute (chunk 9) reads
    // stage 1 (disjoint); iter-9 barrier proved stage-0 readers (chunk 8)
    // drained in all warps. Writes then published by the barrier below.
    float* Dsm = reinterpret_cast<float*>(sm);    // [128][68] stride
#pragma unroll
    for (int t = 0; t < 2; t++)
#pragma unroll
        for (int q = 0; q < 2; q++) {
            int r0 = moff + t * 16 + (lane >> 2);
            int c0 = noff + q * 8 + (lane & 3) * 2;
#pragma unroll
            for (int i = 0; i < 4; i++) {
                float v = acc0[t][q][i] + acc1[t][q][i] + acc2[t][q][i];
                int rr = r0 + (i >> 1) * 8;
                int cc = c0 + (i & 1);
                Dsm[rr * 68 + cc] = v;
            }
        }
    __syncthreads();

#pragma unroll
    for (int i = 0; i < 4; i++) {
        int id = tid + i * 512;      // 0..2047
        int bb = id >> 5;            // 0..63
        int jj = id & 31;
        int b = b0 + bb;
        int jg = j0 + jj;
        float gi = Dsm[(0   + jj) * 68 + bb] + b_ih[jg]           + b_hh[jg];
        float gf = Dsm[(32  + jj) * 68 + bb] + b_ih[HID + jg]     + b_hh[HID + jg];
        float gg = Dsm[(64  + jj) * 68 + bb] + b_ih[2*HID + jg]   + b_hh[2*HID + jg];
        float go = Dsm[(96  + jj) * 68 + bb] + b_ih[3*HID + jg]   + b_hh[3*HID + jg];
        float iv = 1.f / (1.f + expf(-gi));
        float fv = 1.f / (1.f + expf(-gf));
        float gv = tanhf(gg);
        float ov = 1.f / (1.f + expf(-go));
        size_t idx = (size_t)b * HID + jg;
        float cn = fv * c[idx] + iv * gv;
        c[idx] = cn;
        float hv = ov * tanhf(cn);
        h_out[idx] = hv;
        __nv_bfloat16 hh = __float2bfloat16(hv);
        h_hi_out[idx] = hh;
        h_lo_out[idx] = __float2bfloat16(hv - __bfloat162float(hh));
    }
}

// ---------------------------------------------------------------------------
// Conversion kernels
// ---------------------------------------------------------------------------
__global__ void split_mat_kernel(const float* __restrict__ src,
                                 __nv_bfloat16* __restrict__ hi,
                                 __nv_bfloat16* __restrict__ lo, int n) {
    int i = blockIdx.x * blockDim.x + threadIdx.x;
    if (i < n) {
        float v = src[i];
        __nv_bfloat16 h = __float2bfloat16(v);
        hi[i] = h;
        lo[i] = __float2bfloat16(v - __bfloat162float(h));
    }
}

__global__ void split_pad_kernel(const float* __restrict__ src, int srcStride, int srcK,
                                 __nv_bfloat16* __restrict__ hi,
                                 __nv_bfloat16* __restrict__ lo, int rows, int dstK) {
    int i = blockIdx.x * blockDim.x + threadIdx.x;
    if (i < rows * dstK) {
        int r = i / dstK, k = i % dstK;
        float v = (k < srcK) ? src[(size_t)r * srcStride + k] : 0.f;
        __nv_bfloat16 h = __float2bfloat16(v);
        hi[i] = h;
        lo[i] = __float2bfloat16(v - __bfloat162float(h));
    }
}

__global__ void split_src_kernel(const float* __restrict__ src,
                                 __nv_bfloat16* __restrict__ hi,
                                 __nv_bfloat16* __restrict__ lo) {
    int i = blockIdx.x * blockDim.x + threadIdx.x;
    if (i < SRCLEN * BATCH * KPAD) {
        int k = i & (KPAD - 1);
        int sb = i >> 8;
        int b = sb & (BATCH - 1);
        int s = sb >> 8;
        float v = (k < DIN) ? src[((size_t)b * SRCLEN + s) * DIN + k] : 0.f;
        __nv_bfloat16 h = __float2bfloat16(v);
        hi[i] = h;
        lo[i] = __float2bfloat16(v - __bfloat162float(h));
    }
}

// ---------------------------------------------------------------------------
// Output projection fused with feedback split:
// out[b,d] = h[b,:] @ W_out[d,:] + b_out[d]; also writes xd hi/lo (d < DIN).
// ---------------------------------------------------------------------------
__global__ __launch_bounds__(256) void out_proj_kernel(
    const float* __restrict__ h,
    const float* __restrict__ W_out,
    const float* __restrict__ b_out,
    float* __restrict__ out, int out_stride,
    __nv_bfloat16* __restrict__ xd_hi, __nv_bfloat16* __restrict__ xd_lo)
{
    __shared__ float Hs[16][17];
    __shared__ float Wo[16][17];

    const int tid = threadIdx.x;
    const int txd = tid & 15;
    const int tyb = tid >> 4;
    const int d0 = blockIdx.x * 16;
    const int b0 = blockIdx.y * 16;

    float acc = 0.f;
    for (int k0 = 0; k0 < HID; k0 += 16) {
        __syncthreads();
        Hs[txd][tyb] = h[(size_t)(b0 + tyb) * HID + k0 + txd];
        Wo[txd][tyb] = (d0 + tyb < DIN)
            ? W_out[(size_t)(d0 + tyb) * HID + k0 + txd] : 0.f;
        __syncthreads();
#pragma unroll
        for (int k = 0; k < 16; k++)
            acc += Hs[k][tyb] * Wo[k][txd];
    }
    if (d0 + txd < DIN) {
        float v = acc + b_out[d0 + txd];
        out[(size_t)(b0 + tyb) * out_stride + d0 + txd] = v;
        if (xd_hi) {
            size_t xi = (size_t)(b0 + tyb) * KPAD + d0 + txd;
            __nv_bfloat16 hh = __float2bfloat16(v);
            xd_hi[xi] = hh;
            xd_lo[xi] = __float2bfloat16(v - __bfloat162float(hh));
        }
    }
}

// ---------------------------------------------------------------------------
extern "C" void kernel_launch(void* const* d_in, const int* in_sizes, int n_in,
                              void* d_out, int out_size)
{
    const float* src   = (const float*)d_in[0];
    const float* W_ih  = (const float*)d_in[2];
    const float* W_hh  = (const float*)d_in[3];
    const float* b_ih  = (const float*)d_in[4];
    const float* b_hh  = (const float*)d_in[5];
    const float* W_out = (const float*)d_in[6];
    const float* b_out = (const float*)d_in[7];
    float* out = (float*)d_out;

    static bool attr_set = false;
    if (!attr_set) {
        cudaFuncSetAttribute(lstm_mma_step,
                             cudaFuncAttributeMaxDynamicSharedMemorySize, SMEM_TOTAL);
        attr_set = true;
    }

    __nv_bfloat16 *Whh_hi, *Wih_hi, *Xs_hi, *Xs_lo, *xd_hi, *xd_lo, *hhi, *hlo;
    __nv_bfloat16 *Whh_lo, *Wih_lo;
    float *hf, *cc;
    cudaGetSymbolAddress((void**)&Whh_hi, g_Whh_hi);
    cudaGetSymbolAddress((void**)&Whh_lo, g_Whh_lo);
    cudaGetSymbolAddress((void**)&Wih_hi, g_Wih_hi);
    cudaGetSymbolAddress((void**)&Wih_lo, g_Wih_lo);
    cudaGetSymbolAddress((void**)&Xs_hi, g_Xsrc_hi);
    cudaGetSymbolAddress((void**)&Xs_lo, g_Xsrc_lo);
    cudaGetSymbolAddress((void**)&xd_hi, g_xdec_hi);
    cudaGetSymbolAddress((void**)&xd_lo, g_xdec_lo);
    cudaGetSymbolAddress((void**)&hhi, g_hhi);
    cudaGetSymbolAddress((void**)&hlo, g_hlo);
    cudaGetSymbolAddress((void**)&hf, g_hf);
    cudaGetSymbolAddress((void**)&cc, g_c);
    __nv_bfloat16* hhb[2] = {hhi, hhi + BATCH * HID};
    __nv_bfloat16* hlb[2] = {hlo, hlo + BATCH * HID};

    cudaMemsetAsync(hhb[0], 0, (size_t)BATCH * HID * sizeof(__nv_bfloat16));
    cudaMemsetAsync(hlb[0], 0, (size_t)BATCH * HID * sizeof(__nv_bfloat16));
    cudaMemsetAsync(cc, 0, (size_t)BATCH * HID * sizeof(float));
    cudaMemsetAsync(xd_hi, 0, (size_t)BATCH * KPAD * sizeof(__nv_bfloat16));
    cudaMemsetAsync(xd_lo, 0, (size_t)BATCH * KPAD * sizeof(__nv_bfloat16));

    {
        int n = 4096 * HID;
        split_mat_kernel<<<(n + 255) / 256, 256>>>(W_hh, Whh_hi, Whh_lo, n);
        split_pad_kernel<<<(4096 * KPAD + 255) / 256, 256>>>(W_ih, DIN, DIN,
                                                             Wih_hi, Wih_lo, 4096, KPAD);
        int m = SRCLEN * BATCH * KPAD;
        split_src_kernel<<<(m + 255) / 256, 256>>>(src, Xs_hi, Xs_lo);
    }

    dim3 grid(32, 4);
    dim3 pgrid(14, 16);
    int cur = 0;

    // Encoder
    for (int s = 0; s < SRCLEN; s++) {
        lstm_mma_step<<<grid, 512, SMEM_TOTAL>>>(
            Xs_hi + (size_t)s * BATCH * KPAD, Xs_lo + (size_t)s * BATCH * KPAD,
            hhb[cur], hlb[cur], hf, hhb[1 - cur], hlb[1 - cur], cc, b_ih, b_hh);
        cur ^= 1;
    }

    // Decoder
    const __nv_bfloat16* x_hi = Xs_hi + (size_t)(SRCLEN - 1) * BATCH * KPAD;
    const __nv_bfloat16* x_lo = Xs_lo + (size_t)(SRCLEN - 1) * BATCH * KPAD;
    for (int t = 0; t < TGTLEN; t++) {
        lstm_mma_step<<<grid, 512, SMEM_TOTAL>>>(
            x_hi, x_lo, hhb[cur], hlb[cur], hf, hhb[1 - cur], hlb[1 - cur],
            cc, b_ih, b_hh);
        cur ^= 1;
        bool feed = (t + 1 < TGTLEN);
        out_proj_kernel<<<pgrid, 256>>>(hf, W_out, b_out,
                                        out + (size_t)t * DIN, TGTLEN * DIN,
                                        feed ? xd_hi : nullptr,
                                        feed ? xd_lo : nullptr);
        x_hi = xd_hi;
        x_lo = xd_lo;
    }
}